// round 11
// baseline (speedup 1.0000x reference)
#include <cuda_runtime.h>
#include <cuda_fp16.h>
#include <math.h>

#define MAXN 100000
#define MAXEP (1600000 + 3 * 100000 + 32)   // CSR padded to 4-edge granularity

// ---------------- scratch ----------------
__device__ int     g_indeg[MAXN];
__device__ int     g_rowstart[MAXN];
__device__ int     g_cursor[MAXN];
__device__ int     g_bsum[256];
__device__ float   g_dis[MAXN];
__device__ __align__(16) int g_csr[MAXEP];
__device__ __half2 g_h0h[(size_t)(MAXN + 1) * 32];  // +1 zero dummy row for padding
__device__ float   g_h [(size_t)MAXN * 64];
__device__ __half2 g_ggh[(size_t)(MAXN + 1) * 32];  // +1 zero dummy row
__device__ __half  g_zh [(size_t)MAXN * 32];

// ---------------- graph preprocessing ----------------
__global__ void init_kernel(int n) {
    int i = blockIdx.x * blockDim.x + threadIdx.x;
    if (i < n) g_indeg[i] = 0;
}

__global__ void hist_kernel(const int* __restrict__ dst, int E) {
    int e = blockIdx.x * blockDim.x + threadIdx.x;
    if (e < E) atomicAdd(&g_indeg[dst[e]], 1);
}

__global__ void dis_kernel(int n) {
    int i = blockIdx.x * blockDim.x + threadIdx.x;
    if (i < n) g_dis[i] = rsqrtf((float)(g_indeg[i] + 1));
    if (i < 32) {                       // zero the dummy row used by CSR padding
        __half2 z = __floats2half2_rn(0.f, 0.f);
        g_h0h[(size_t)n * 32 + i] = z;
        g_ggh[(size_t)n * 32 + i] = z;
    }
}

__global__ void scan1_kernel(int n) {
    __shared__ int sm[1024];
    int t = threadIdx.x;
    int i = blockIdx.x * 1024 + t;
    int v = 0;
    if (i < n) v = (g_indeg[i] + 3) & ~3;      // padded count
    sm[t] = v;
    __syncthreads();
#pragma unroll
    for (int o = 1; o < 1024; o <<= 1) {
        int tv = (t >= o) ? sm[t - o] : 0;
        __syncthreads();
        sm[t] += tv;
        __syncthreads();
    }
    if (i < n) g_rowstart[i] = sm[t] - v;
    if (t == 1023) g_bsum[blockIdx.x] = sm[1023];
}

__global__ void scan2_kernel(int nb) {
    __shared__ int sm[256];
    int t = threadIdx.x;
    int v = (t < nb) ? g_bsum[t] : 0;
    sm[t] = v;
    __syncthreads();
#pragma unroll
    for (int o = 1; o < 256; o <<= 1) {
        int tv = (t >= o) ? sm[t - o] : 0;
        __syncthreads();
        sm[t] += tv;
        __syncthreads();
    }
    if (t < nb) g_bsum[t] = sm[t] - v;
}

__global__ void scan3_kernel(int n) {
    int i = blockIdx.x * blockDim.x + threadIdx.x;
    if (i < n) {
        int v = g_rowstart[i] + g_bsum[i >> 10];
        g_rowstart[i] = v;
        g_cursor[i]   = v;
        int cnt  = g_indeg[i];
        int pcnt = (cnt + 3) & ~3;
        for (int p = v + cnt; p < v + pcnt; p++) g_csr[p] = n;  // dummy (zero row)
    }
}

__global__ void fill_kernel(const int* __restrict__ src, const int* __restrict__ dst, int E) {
    int e = blockIdx.x * blockDim.x + threadIdx.x;
    if (e < E) {
        int p = atomicAdd(&g_cursor[dst[e]], 1);
        g_csr[p] = src[e];
    }
}

// ============ GEMM 1 (R7 config): 128 rows/block, thread = 4 rows x 8 cols ============
__global__ void __launch_bounds__(256) gemm1_kernel(const float* __restrict__ x,
                                                    const float* __restrict__ W, int n) {
    extern __shared__ float sm[];
    float* wsa = sm;
    float* wsb = sm + 4096;
    float* xs  = sm + 8192;
    int tid = threadIdx.x;
    for (int i = tid; i < 128 * 64; i += 256) {
        int k = i >> 6, j = i & 63;
        float v = W[i];
        int jt = j >> 3, c = j & 7;
        if (c < 4) wsa[k * 32 + jt * 4 + c] = v;
        else       wsb[k * 32 + jt * 4 + (c - 4)] = v;
    }
    int row0 = blockIdx.x * 128;
    int lane = tid & 31, wrp = tid >> 5;
    int rg4 = (wrp * 4 + (lane >> 3)) * 4;
    int jt  = lane & 7;
    float acc[4][8];
#pragma unroll
    for (int i = 0; i < 4; i++)
#pragma unroll
        for (int j = 0; j < 8; j++) acc[i][j] = 0.f;

    int frow = tid >> 3;
    int kq   = tid & 7;
    int csw  = ((kq & 3) << 3) | ((kq >> 2) << 2);

    for (int kc = 0; kc < 4; kc++) {
        __syncthreads();
#pragma unroll
        for (int it = 0; it < 4; it++) {
            int row  = frow + it * 32;
            int grow = row0 + row;
            float4 v = (grow < n) ? *(const float4*)(x + (size_t)grow * 128 + kc * 32 + kq * 4)
                                  : make_float4(0.f, 0.f, 0.f, 0.f);
            int rs = row ^ csw;
            xs[(kq * 4 + 0) * 132 + rs] = v.x;
            xs[(kq * 4 + 1) * 132 + rs] = v.y;
            xs[(kq * 4 + 2) * 132 + rs] = v.z;
            xs[(kq * 4 + 3) * 132 + rs] = v.w;
        }
        __syncthreads();
#pragma unroll
        for (int kk = 0; kk < 32; kk++) {
            int c = (((kk >> 2) & 3) << 3) | (((kk >> 4) & 1) << 2);
            float4 xv = *(const float4*)(xs + kk * 132 + (rg4 ^ c));
            int k = kc * 32 + kk;
            float4 a = *(const float4*)(wsa + k * 32 + jt * 4);
            float4 b = *(const float4*)(wsb + k * 32 + jt * 4);
            float xr[4] = {xv.x, xv.y, xv.z, xv.w};
#pragma unroll
            for (int i = 0; i < 4; i++) {
                acc[i][0] = fmaf(xr[i], a.x, acc[i][0]);
                acc[i][1] = fmaf(xr[i], a.y, acc[i][1]);
                acc[i][2] = fmaf(xr[i], a.z, acc[i][2]);
                acc[i][3] = fmaf(xr[i], a.w, acc[i][3]);
                acc[i][4] = fmaf(xr[i], b.x, acc[i][4]);
                acc[i][5] = fmaf(xr[i], b.y, acc[i][5]);
                acc[i][6] = fmaf(xr[i], b.z, acc[i][6]);
                acc[i][7] = fmaf(xr[i], b.w, acc[i][7]);
            }
        }
    }
#pragma unroll
    for (int i = 0; i < 4; i++) {
        int rr = row0 + rg4 + i;
        if (rr < n) {
            float di = g_dis[rr];
            __half2* o = g_h0h + (size_t)rr * 32 + jt * 4;
            o[0] = __floats2half2_rn(di*acc[i][0], di*acc[i][1]);
            o[1] = __floats2half2_rn(di*acc[i][2], di*acc[i][3]);
            o[2] = __floats2half2_rn(di*acc[i][4], di*acc[i][5]);
            o[3] = __floats2half2_rn(di*acc[i][6], di*acc[i][7]);
        }
    }
}

// ====== GEMM 2 (R7 config) ======
__global__ void __launch_bounds__(256) gemm2_kernel(const float* __restrict__ Wmu,
                                                    const float* __restrict__ Wls, int n) {
    extern __shared__ float sm[];
    float* wsa = sm;
    float* wsb = sm + 2048;
    float* xs  = sm + 4096;
    int tid = threadIdx.x;
    for (int i = tid; i < 64 * 64; i += 256) {
        int k = i >> 6, j = i & 63;
        float v = (j < 32) ? Wmu[k * 32 + j] : Wls[k * 32 + (j - 32)];
        int jn = (j < 32) ? (2 * j) : (2 * (j - 32) + 1);
        int jt = jn >> 3, c = jn & 7;
        if (c < 4) wsa[k * 32 + jt * 4 + c] = v;
        else       wsb[k * 32 + jt * 4 + (c - 4)] = v;
    }
    int row0 = blockIdx.x * 128;
    int lane = tid & 31, wrp = tid >> 5;
    int rg4 = (wrp * 4 + (lane >> 3)) * 4;
    int jt  = lane & 7;
    float acc[4][8];
#pragma unroll
    for (int i = 0; i < 4; i++)
#pragma unroll
        for (int j = 0; j < 8; j++) acc[i][j] = 0.f;

    int frow = tid >> 3;
    int kq   = tid & 7;
    int csw  = ((kq & 3) << 3) | ((kq >> 2) << 2);

    for (int kc = 0; kc < 2; kc++) {
        __syncthreads();
#pragma unroll
        for (int it = 0; it < 4; it++) {
            int row  = frow + it * 32;
            int grow = row0 + row;
            float4 v = (grow < n) ? *(const float4*)(g_h + (size_t)grow * 64 + kc * 32 + kq * 4)
                                  : make_float4(0.f, 0.f, 0.f, 0.f);
            int rs = row ^ csw;
            xs[(kq * 4 + 0) * 132 + rs] = v.x;
            xs[(kq * 4 + 1) * 132 + rs] = v.y;
            xs[(kq * 4 + 2) * 132 + rs] = v.z;
            xs[(kq * 4 + 3) * 132 + rs] = v.w;
        }
        __syncthreads();
#pragma unroll
        for (int kk = 0; kk < 32; kk++) {
            int c = (((kk >> 2) & 3) << 3) | (((kk >> 4) & 1) << 2);
            float4 xv = *(const float4*)(xs + kk * 132 + (rg4 ^ c));
            int k = kc * 32 + kk;
            float4 a = *(const float4*)(wsa + k * 32 + jt * 4);
            float4 b = *(const float4*)(wsb + k * 32 + jt * 4);
            float xr[4] = {xv.x, xv.y, xv.z, xv.w};
#pragma unroll
            for (int i = 0; i < 4; i++) {
                acc[i][0] = fmaf(xr[i], a.x, acc[i][0]);
                acc[i][1] = fmaf(xr[i], a.y, acc[i][1]);
                acc[i][2] = fmaf(xr[i], a.z, acc[i][2]);
                acc[i][3] = fmaf(xr[i], a.w, acc[i][3]);
                acc[i][4] = fmaf(xr[i], b.x, acc[i][4]);
                acc[i][5] = fmaf(xr[i], b.y, acc[i][5]);
                acc[i][6] = fmaf(xr[i], b.z, acc[i][6]);
                acc[i][7] = fmaf(xr[i], b.w, acc[i][7]);
            }
        }
    }
#pragma unroll
    for (int i = 0; i < 4; i++) {
        int rr = row0 + rg4 + i;
        if (rr < n) {
            float di = g_dis[rr];
            __half2* o = g_ggh + (size_t)rr * 32 + jt * 4;
            o[0] = __floats2half2_rn(di*acc[i][0], di*acc[i][1]);
            o[1] = __floats2half2_rn(di*acc[i][2], di*acc[i][3]);
            o[2] = __floats2half2_rn(di*acc[i][4], di*acc[i][5]);
            o[3] = __floats2half2_rn(di*acc[i][6], di*acc[i][7]);
        }
    }
}

// ---------------- Conv1: warp/node, int4 index loads over padded CSR ----------------
__global__ void __launch_bounds__(256) conv1_kernel(const float* __restrict__ b1, int n) {
    int node = blockIdx.x * 8 + (threadIdx.x >> 5);
    int t    = threadIdx.x & 31;
    if (node >= n) return;
    int st   = g_rowstart[node];
    int pcnt = (g_indeg[node] + 3) & ~3;
    const int4* cs4 = (const int4*)(g_csr + st);
    const __half2* hb = g_h0h + t;
    float a0x = 0.f, a0y = 0.f, a1x = 0.f, a1y = 0.f;
    int nb4 = pcnt >> 2;
    int b = 0;
    for (; b + 2 <= nb4; b += 2) {
        int4 i0 = cs4[b], i1 = cs4[b + 1];
        float2 v0 = __half22float2(hb[(size_t)i0.x * 32]);
        float2 v1 = __half22float2(hb[(size_t)i0.y * 32]);
        float2 v2 = __half22float2(hb[(size_t)i0.z * 32]);
        float2 v3 = __half22float2(hb[(size_t)i0.w * 32]);
        float2 v4 = __half22float2(hb[(size_t)i1.x * 32]);
        float2 v5 = __half22float2(hb[(size_t)i1.y * 32]);
        float2 v6 = __half22float2(hb[(size_t)i1.z * 32]);
        float2 v7 = __half22float2(hb[(size_t)i1.w * 32]);
        a0x += v0.x; a0y += v0.y; a1x += v1.x; a1y += v1.y;
        a0x += v2.x; a0y += v2.y; a1x += v3.x; a1y += v3.y;
        a0x += v4.x; a0y += v4.y; a1x += v5.x; a1y += v5.y;
        a0x += v6.x; a0y += v6.y; a1x += v7.x; a1y += v7.y;
    }
    if (b < nb4) {
        int4 i0 = cs4[b];
        float2 v0 = __half22float2(hb[(size_t)i0.x * 32]);
        float2 v1 = __half22float2(hb[(size_t)i0.y * 32]);
        float2 v2 = __half22float2(hb[(size_t)i0.z * 32]);
        float2 v3 = __half22float2(hb[(size_t)i0.w * 32]);
        a0x += v0.x; a0y += v0.y; a1x += v1.x; a1y += v1.y;
        a0x += v2.x; a0y += v2.y; a1x += v3.x; a1y += v3.y;
    }
    float2 self = __half22float2(hb[(size_t)node * 32]);
    float sx = a0x + a1x + self.x;
    float sy = a0y + a1y + self.y;
    float di = g_dis[node];
    float2 bb = *(const float2*)(b1 + 2 * t);
    float vx = fmaxf(fmaf(di, sx, bb.x), 0.f);
    float vy = fmaxf(fmaf(di, sy, bb.y), 0.f);
    float ss = vx * vx + vy * vy;
#pragma unroll
    for (int o = 16; o > 0; o >>= 1) ss += __shfl_xor_sync(0xffffffffu, ss, o);
    float scale = 1.0f / fmaxf(sqrtf(ss), 1e-12f);
    *(float2*)(g_h + (size_t)node * 64 + 2 * t) = make_float2(vx * scale, vy * scale);
}

// ---------------- Conv2 + reparametrize: int4 index loads ----------------
__global__ void __launch_bounds__(256) conv2_kernel(const float* __restrict__ bmu,
                                                    const float* __restrict__ bls,
                                                    const float* __restrict__ eps,
                                                    float* __restrict__ out_mu,
                                                    float* __restrict__ out_ls, int n) {
    int node = blockIdx.x * 8 + (threadIdx.x >> 5);
    int t    = threadIdx.x & 31;
    if (node >= n) return;
    int st   = g_rowstart[node];
    int pcnt = (g_indeg[node] + 3) & ~3;
    const int4* cs4 = (const int4*)(g_csr + st);
    const __half2* gb = g_ggh + t;
    float a0x = 0.f, a0y = 0.f, a1x = 0.f, a1y = 0.f;
    int nb4 = pcnt >> 2;
    int b = 0;
    for (; b + 2 <= nb4; b += 2) {
        int4 i0 = cs4[b], i1 = cs4[b + 1];
        float2 v0 = __half22float2(gb[(size_t)i0.x * 32]);
        float2 v1 = __half22float2(gb[(size_t)i0.y * 32]);
        float2 v2 = __half22float2(gb[(size_t)i0.z * 32]);
        float2 v3 = __half22float2(gb[(size_t)i0.w * 32]);
        float2 v4 = __half22float2(gb[(size_t)i1.x * 32]);
        float2 v5 = __half22float2(gb[(size_t)i1.y * 32]);
        float2 v6 = __half22float2(gb[(size_t)i1.z * 32]);
        float2 v7 = __half22float2(gb[(size_t)i1.w * 32]);
        a0x += v0.x; a0y += v0.y; a1x += v1.x; a1y += v1.y;
        a0x += v2.x; a0y += v2.y; a1x += v3.x; a1y += v3.y;
        a0x += v4.x; a0y += v4.y; a1x += v5.x; a1y += v5.y;
        a0x += v6.x; a0y += v6.y; a1x += v7.x; a1y += v7.y;
    }
    if (b < nb4) {
        int4 i0 = cs4[b];
        float2 v0 = __half22float2(gb[(size_t)i0.x * 32]);
        float2 v1 = __half22float2(gb[(size_t)i0.y * 32]);
        float2 v2 = __half22float2(gb[(size_t)i0.z * 32]);
        float2 v3 = __half22float2(gb[(size_t)i0.w * 32]);
        a0x += v0.x; a0y += v0.y; a1x += v1.x; a1y += v1.y;
        a0x += v2.x; a0y += v2.y; a1x += v3.x; a1y += v3.y;
    }
    float2 self = __half22float2(gb[(size_t)node * 32]);
    float sx = a0x + a1x + self.x;
    float sy = a0y + a1y + self.y;
    float di = g_dis[node];
    float mu = fmaf(di, sx, bmu[t]);
    float ls = fmaf(di, sy, bls[t]);
    size_t oi = (size_t)node * 32 + t;
    out_mu[oi] = mu;
    out_ls[oi] = ls;
    float lc = fminf(fmaxf(ls, -10.f), 10.f);
    g_zh[oi] = __float2half_rn(fmaf(eps[oi], __expf(lc), mu));
}

// ---------------- decode: 4 lanes/edge, uint4 (16B) loads ----------------
__global__ void __launch_bounds__(256) decode_kernel(const int* __restrict__ src,
                                                     const int* __restrict__ dst,
                                                     float* __restrict__ out, int E) {
    int gid = blockIdx.x * 256 + threadIdx.x;
    int e   = gid >> 2;
    int sub = gid & 3;
    if (e >= E) return;
    int s = src[e], d = dst[e];
    uint4 ua = *(const uint4*)(g_zh + (size_t)s * 32 + sub * 8);
    uint4 ub = *(const uint4*)(g_zh + (size_t)d * 32 + sub * 8);
    float2 a0 = __half22float2(*reinterpret_cast<__half2*>(&ua.x));
    float2 a1 = __half22float2(*reinterpret_cast<__half2*>(&ua.y));
    float2 a2 = __half22float2(*reinterpret_cast<__half2*>(&ua.z));
    float2 a3 = __half22float2(*reinterpret_cast<__half2*>(&ua.w));
    float2 b0 = __half22float2(*reinterpret_cast<__half2*>(&ub.x));
    float2 b1 = __half22float2(*reinterpret_cast<__half2*>(&ub.y));
    float2 b2 = __half22float2(*reinterpret_cast<__half2*>(&ub.z));
    float2 b3 = __half22float2(*reinterpret_cast<__half2*>(&ub.w));
    float p = a0.x*b0.x + a0.y*b0.y + a1.x*b1.x + a1.y*b1.y
            + a2.x*b2.x + a2.y*b2.y + a3.x*b3.x + a3.y*b3.y;
    p += __shfl_xor_sync(0xffffffffu, p, 1);
    p += __shfl_xor_sync(0xffffffffu, p, 2);
    if (sub == 0) out[e] = 1.0f / (1.0f + __expf(-p));
}

// ---------------- launch ----------------
extern "C" void kernel_launch(void* const* d_in, const int* in_sizes, int n_in,
                              void* d_out, int out_size) {
    const float* x   = (const float*)d_in[0];
    const int*   ei  = (const int*)  d_in[1];
    const float* eps = (const float*)d_in[2];
    const float* W1  = (const float*)d_in[3];
    const float* b1  = (const float*)d_in[4];
    const float* Wmu = (const float*)d_in[5];
    const float* bmu = (const float*)d_in[6];
    const float* Wls = (const float*)d_in[7];
    const float* bls = (const float*)d_in[8];

    int n = in_sizes[0] / 128;
    int E = in_sizes[1] / 2;
    const int* src = ei;
    const int* dst = ei + E;

    float* out     = (float*)d_out;
    float* out_adj = out;
    float* out_mu  = out + E;
    float* out_ls  = out + E + (size_t)n * 32;

    const int SMEM1 = (4096 + 4096 + 32 * 132) * 4;   // 49664
    const int SMEM2 = (2048 + 2048 + 32 * 132) * 4;   // 33280
    cudaFuncSetAttribute(gemm1_kernel, cudaFuncAttributeMaxDynamicSharedMemorySize, SMEM1);
    cudaFuncSetAttribute(gemm2_kernel, cudaFuncAttributeMaxDynamicSharedMemorySize, SMEM2);

    cudaStream_t s2;
    cudaEvent_t evFork, evJoin;
    cudaStreamCreateWithFlags(&s2, cudaStreamNonBlocking);
    cudaEventCreateWithFlags(&evFork, cudaEventDisableTiming);
    cudaEventCreateWithFlags(&evJoin, cudaEventDisableTiming);

    init_kernel<<<(n + 255) / 256, 256>>>(n);
    hist_kernel<<<(E + 255) / 256, 256>>>(dst, E);
    dis_kernel<<<(n + 255) / 256, 256>>>(n);

    // fork: gemm1 depends only on {x, W1, dis}
    cudaEventRecord(evFork, 0);
    cudaStreamWaitEvent(s2, evFork, 0);
    gemm1_kernel<<<(n + 127) / 128, 256, SMEM1, s2>>>(x, W1, n);
    cudaEventRecord(evJoin, s2);

    int nb = (n + 1023) / 1024;
    scan1_kernel<<<nb, 1024>>>(n);
    scan2_kernel<<<1, 256>>>(nb);
    scan3_kernel<<<(n + 255) / 256, 256>>>(n);
    fill_kernel<<<(E + 255) / 256, 256>>>(src, dst, E);

    cudaStreamWaitEvent(0, evJoin, 0);

    conv1_kernel<<<(n + 7) / 8, 256>>>(b1, n);
    gemm2_kernel<<<(n + 127) / 128, 256, SMEM2>>>(Wmu, Wls, n);
    conv2_kernel<<<(n + 7) / 8, 256>>>(bmu, bls, eps, out_mu, out_ls, n);
    decode_kernel<<<((size_t)E * 4 + 255) / 256, 256>>>(src, dst, out_adj, E);
}

// round 12
// speedup vs baseline: 1.4114x; 1.4114x over previous
#include <cuda_runtime.h>
#include <cuda_fp16.h>
#include <math.h>

#define MAXN 100000
#define MAXE 1600000

// ---------------- scratch ----------------
__device__ int     g_indeg[MAXN];
__device__ int     g_rowstart[MAXN];
__device__ int     g_cursor[MAXN];
__device__ int     g_bsum[256];
__device__ float   g_dis[MAXN];
__device__ int     g_csr[MAXE];
__device__ __half2 g_h0h[(size_t)MAXN * 32];    // fp16 dis-prescaled x@W1
__device__ float   g_h [(size_t)MAXN * 64];     // fp32 normalized hidden
__device__ __half2 g_ggh[(size_t)MAXN * 32];    // fp16 dis-prescaled (mu,ls) interleaved
__device__ __half  g_zh [(size_t)MAXN * 32];    // fp16 z

// ---------------- graph preprocessing ----------------
__global__ void init_kernel(int n) {
    int i = blockIdx.x * blockDim.x + threadIdx.x;
    if (i < n) g_indeg[i] = 0;
}

__global__ void hist_kernel(const int* __restrict__ dst, int E) {
    int e = blockIdx.x * blockDim.x + threadIdx.x;
    if (e < E) atomicAdd(&g_indeg[dst[e]], 1);
}

__global__ void dis_kernel(int n) {
    int i = blockIdx.x * blockDim.x + threadIdx.x;
    if (i < n) g_dis[i] = rsqrtf((float)(g_indeg[i] + 1));
}

__global__ void scan1_kernel(int n) {
    __shared__ int sm[1024];
    int t = threadIdx.x;
    int i = blockIdx.x * 1024 + t;
    int v = (i < n) ? g_indeg[i] : 0;
    sm[t] = v;
    __syncthreads();
#pragma unroll
    for (int o = 1; o < 1024; o <<= 1) {
        int tv = (t >= o) ? sm[t - o] : 0;
        __syncthreads();
        sm[t] += tv;
        __syncthreads();
    }
    if (i < n) g_rowstart[i] = sm[t] - v;
    if (t == 1023) g_bsum[blockIdx.x] = sm[1023];
}

__global__ void scan2_kernel(int nb) {
    __shared__ int sm[256];
    int t = threadIdx.x;
    int v = (t < nb) ? g_bsum[t] : 0;
    sm[t] = v;
    __syncthreads();
#pragma unroll
    for (int o = 1; o < 256; o <<= 1) {
        int tv = (t >= o) ? sm[t - o] : 0;
        __syncthreads();
        sm[t] += tv;
        __syncthreads();
    }
    if (t < nb) g_bsum[t] = sm[t] - v;
}

__global__ void scan3_kernel(int n) {
    int i = blockIdx.x * blockDim.x + threadIdx.x;
    if (i < n) {
        int v = g_rowstart[i] + g_bsum[i >> 10];
        g_rowstart[i] = v;
        g_cursor[i]   = v;
    }
}

__global__ void fill_kernel(const int* __restrict__ src, const int* __restrict__ dst, int E) {
    int e = blockIdx.x * blockDim.x + threadIdx.x;
    if (e < E) {
        int p = atomicAdd(&g_cursor[dst[e]], 1);
        g_csr[p] = src[e];
    }
}

// ============ GEMM 1 (R7/R10 config): 128 rows/block, thread = 4 rows x 8 cols ============
__global__ void __launch_bounds__(256) gemm1_kernel(const float* __restrict__ x,
                                                    const float* __restrict__ W, int n) {
    extern __shared__ float sm[];
    float* wsa = sm;
    float* wsb = sm + 4096;
    float* xs  = sm + 8192;
    int tid = threadIdx.x;
    for (int i = tid; i < 128 * 64; i += 256) {
        int k = i >> 6, j = i & 63;
        float v = W[i];
        int jt = j >> 3, c = j & 7;
        if (c < 4) wsa[k * 32 + jt * 4 + c] = v;
        else       wsb[k * 32 + jt * 4 + (c - 4)] = v;
    }
    int row0 = blockIdx.x * 128;
    int lane = tid & 31, wrp = tid >> 5;
    int rg4 = (wrp * 4 + (lane >> 3)) * 4;
    int jt  = lane & 7;
    float acc[4][8];
#pragma unroll
    for (int i = 0; i < 4; i++)
#pragma unroll
        for (int j = 0; j < 8; j++) acc[i][j] = 0.f;

    int frow = tid >> 3;
    int kq   = tid & 7;
    int csw  = ((kq & 3) << 3) | ((kq >> 2) << 2);

    for (int kc = 0; kc < 4; kc++) {
        __syncthreads();
#pragma unroll
        for (int it = 0; it < 4; it++) {
            int row  = frow + it * 32;
            int grow = row0 + row;
            float4 v = (grow < n) ? *(const float4*)(x + (size_t)grow * 128 + kc * 32 + kq * 4)
                                  : make_float4(0.f, 0.f, 0.f, 0.f);
            int rs = row ^ csw;
            xs[(kq * 4 + 0) * 132 + rs] = v.x;
            xs[(kq * 4 + 1) * 132 + rs] = v.y;
            xs[(kq * 4 + 2) * 132 + rs] = v.z;
            xs[(kq * 4 + 3) * 132 + rs] = v.w;
        }
        __syncthreads();
#pragma unroll
        for (int kk = 0; kk < 32; kk++) {
            int c = (((kk >> 2) & 3) << 3) | (((kk >> 4) & 1) << 2);
            float4 xv = *(const float4*)(xs + kk * 132 + (rg4 ^ c));
            int k = kc * 32 + kk;
            float4 a = *(const float4*)(wsa + k * 32 + jt * 4);
            float4 b = *(const float4*)(wsb + k * 32 + jt * 4);
            float xr[4] = {xv.x, xv.y, xv.z, xv.w};
#pragma unroll
            for (int i = 0; i < 4; i++) {
                acc[i][0] = fmaf(xr[i], a.x, acc[i][0]);
                acc[i][1] = fmaf(xr[i], a.y, acc[i][1]);
                acc[i][2] = fmaf(xr[i], a.z, acc[i][2]);
                acc[i][3] = fmaf(xr[i], a.w, acc[i][3]);
                acc[i][4] = fmaf(xr[i], b.x, acc[i][4]);
                acc[i][5] = fmaf(xr[i], b.y, acc[i][5]);
                acc[i][6] = fmaf(xr[i], b.z, acc[i][6]);
                acc[i][7] = fmaf(xr[i], b.w, acc[i][7]);
            }
        }
    }
#pragma unroll
    for (int i = 0; i < 4; i++) {
        int rr = row0 + rg4 + i;
        if (rr < n) {
            float di = g_dis[rr];
            __half2* o = g_h0h + (size_t)rr * 32 + jt * 4;
            o[0] = __floats2half2_rn(di*acc[i][0], di*acc[i][1]);
            o[1] = __floats2half2_rn(di*acc[i][2], di*acc[i][3]);
            o[2] = __floats2half2_rn(di*acc[i][4], di*acc[i][5]);
            o[3] = __floats2half2_rn(di*acc[i][6], di*acc[i][7]);
        }
    }
}

// ====== GEMM 2 (R7/R10 config) ======
__global__ void __launch_bounds__(256) gemm2_kernel(const float* __restrict__ Wmu,
                                                    const float* __restrict__ Wls, int n) {
    extern __shared__ float sm[];
    float* wsa = sm;
    float* wsb = sm + 2048;
    float* xs  = sm + 4096;
    int tid = threadIdx.x;
    for (int i = tid; i < 64 * 64; i += 256) {
        int k = i >> 6, j = i & 63;
        float v = (j < 32) ? Wmu[k * 32 + j] : Wls[k * 32 + (j - 32)];
        int jn = (j < 32) ? (2 * j) : (2 * (j - 32) + 1);
        int jt = jn >> 3, c = jn & 7;
        if (c < 4) wsa[k * 32 + jt * 4 + c] = v;
        else       wsb[k * 32 + jt * 4 + (c - 4)] = v;
    }
    int row0 = blockIdx.x * 128;
    int lane = tid & 31, wrp = tid >> 5;
    int rg4 = (wrp * 4 + (lane >> 3)) * 4;
    int jt  = lane & 7;
    float acc[4][8];
#pragma unroll
    for (int i = 0; i < 4; i++)
#pragma unroll
        for (int j = 0; j < 8; j++) acc[i][j] = 0.f;

    int frow = tid >> 3;
    int kq   = tid & 7;
    int csw  = ((kq & 3) << 3) | ((kq >> 2) << 2);

    for (int kc = 0; kc < 2; kc++) {
        __syncthreads();
#pragma unroll
        for (int it = 0; it < 4; it++) {
            int row  = frow + it * 32;
            int grow = row0 + row;
            float4 v = (grow < n) ? *(const float4*)(g_h + (size_t)grow * 64 + kc * 32 + kq * 4)
                                  : make_float4(0.f, 0.f, 0.f, 0.f);
            int rs = row ^ csw;
            xs[(kq * 4 + 0) * 132 + rs] = v.x;
            xs[(kq * 4 + 1) * 132 + rs] = v.y;
            xs[(kq * 4 + 2) * 132 + rs] = v.z;
            xs[(kq * 4 + 3) * 132 + rs] = v.w;
        }
        __syncthreads();
#pragma unroll
        for (int kk = 0; kk < 32; kk++) {
            int c = (((kk >> 2) & 3) << 3) | (((kk >> 4) & 1) << 2);
            float4 xv = *(const float4*)(xs + kk * 132 + (rg4 ^ c));
            int k = kc * 32 + kk;
            float4 a = *(const float4*)(wsa + k * 32 + jt * 4);
            float4 b = *(const float4*)(wsb + k * 32 + jt * 4);
            float xr[4] = {xv.x, xv.y, xv.z, xv.w};
#pragma unroll
            for (int i = 0; i < 4; i++) {
                acc[i][0] = fmaf(xr[i], a.x, acc[i][0]);
                acc[i][1] = fmaf(xr[i], a.y, acc[i][1]);
                acc[i][2] = fmaf(xr[i], a.z, acc[i][2]);
                acc[i][3] = fmaf(xr[i], a.w, acc[i][3]);
                acc[i][4] = fmaf(xr[i], b.x, acc[i][4]);
                acc[i][5] = fmaf(xr[i], b.y, acc[i][5]);
                acc[i][6] = fmaf(xr[i], b.z, acc[i][6]);
                acc[i][7] = fmaf(xr[i], b.w, acc[i][7]);
            }
        }
    }
#pragma unroll
    for (int i = 0; i < 4; i++) {
        int rr = row0 + rg4 + i;
        if (rr < n) {
            float di = g_dis[rr];
            __half2* o = g_ggh + (size_t)rr * 32 + jt * 4;
            o[0] = __floats2half2_rn(di*acc[i][0], di*acc[i][1]);
            o[1] = __floats2half2_rn(di*acc[i][2], di*acc[i][3]);
            o[2] = __floats2half2_rn(di*acc[i][4], di*acc[i][5]);
            o[3] = __floats2half2_rn(di*acc[i][6], di*acc[i][7]);
        }
    }
}

// -------- Conv1: HALF-WARP per node (2 nodes/warp), lane covers 4 features --------
__global__ void __launch_bounds__(256) conv1_kernel(const float* __restrict__ b1, int n) {
    int node = blockIdx.x * 16 + (threadIdx.x >> 4);
    int t    = threadIdx.x & 15;
    bool valid = node < n;
    int nd = valid ? node : 0;
    int st  = g_rowstart[nd];
    int cnt = valid ? g_indeg[nd] : 0;
    const int* cs = g_csr + st;
    const __half2* hb = g_h0h + 2 * t;   // half2 idx 2t, 2t+1 = features 4t..4t+3
    float a0x=0.f,a0y=0.f,a0z=0.f,a0w=0.f, a1x=0.f,a1y=0.f,a1z=0.f,a1w=0.f;
    int e = 0;
    for (; e + 4 <= cnt; e += 4) {
        int s0 = cs[e], s1 = cs[e+1], s2 = cs[e+2], s3 = cs[e+3];
        uint2 u0 = *(const uint2*)(hb + (size_t)s0 * 32);
        uint2 u1 = *(const uint2*)(hb + (size_t)s1 * 32);
        uint2 u2 = *(const uint2*)(hb + (size_t)s2 * 32);
        uint2 u3 = *(const uint2*)(hb + (size_t)s3 * 32);
        float2 p0 = __half22float2(*(__half2*)&u0.x), q0 = __half22float2(*(__half2*)&u0.y);
        float2 p1 = __half22float2(*(__half2*)&u1.x), q1 = __half22float2(*(__half2*)&u1.y);
        float2 p2 = __half22float2(*(__half2*)&u2.x), q2 = __half22float2(*(__half2*)&u2.y);
        float2 p3 = __half22float2(*(__half2*)&u3.x), q3 = __half22float2(*(__half2*)&u3.y);
        a0x += p0.x; a0y += p0.y; a0z += q0.x; a0w += q0.y;
        a1x += p1.x; a1y += p1.y; a1z += q1.x; a1w += q1.y;
        a0x += p2.x; a0y += p2.y; a0z += q2.x; a0w += q2.y;
        a1x += p3.x; a1y += p3.y; a1z += q3.x; a1w += q3.y;
    }
    for (; e < cnt; e++) {
        uint2 u = *(const uint2*)(hb + (size_t)cs[e] * 32);
        float2 p = __half22float2(*(__half2*)&u.x), q = __half22float2(*(__half2*)&u.y);
        a0x += p.x; a0y += p.y; a0z += q.x; a0w += q.y;
    }
    uint2 us = *(const uint2*)(hb + (size_t)nd * 32);
    float2 ps = __half22float2(*(__half2*)&us.x), qs = __half22float2(*(__half2*)&us.y);
    float sx = a0x + a1x + ps.x;
    float sy = a0y + a1y + ps.y;
    float sz = a0z + a1z + qs.x;
    float sw = a0w + a1w + qs.y;
    float di = g_dis[nd];
    float4 bb = *(const float4*)(b1 + 4 * t);
    float vx = fmaxf(fmaf(di, sx, bb.x), 0.f);
    float vy = fmaxf(fmaf(di, sy, bb.y), 0.f);
    float vz = fmaxf(fmaf(di, sz, bb.z), 0.f);
    float vw = fmaxf(fmaf(di, sw, bb.w), 0.f);
    float ss = vx*vx + vy*vy + vz*vz + vw*vw;
#pragma unroll
    for (int o = 8; o > 0; o >>= 1) ss += __shfl_xor_sync(0xffffffffu, ss, o);
    float scale = 1.0f / fmaxf(sqrtf(ss), 1e-12f);
    if (valid)
        *(float4*)(g_h + (size_t)nd * 64 + 4 * t) =
            make_float4(vx*scale, vy*scale, vz*scale, vw*scale);
}

// -------- Conv2 + reparametrize: HALF-WARP per node, lane covers (mu,ls) pairs 2t,2t+1 --------
__global__ void __launch_bounds__(256) conv2_kernel(const float* __restrict__ bmu,
                                                    const float* __restrict__ bls,
                                                    const float* __restrict__ eps,
                                                    float* __restrict__ out_mu,
                                                    float* __restrict__ out_ls, int n) {
    int node = blockIdx.x * 16 + (threadIdx.x >> 4);
    int t    = threadIdx.x & 15;
    bool valid = node < n;
    int nd = valid ? node : 0;
    int st  = g_rowstart[nd];
    int cnt = valid ? g_indeg[nd] : 0;
    const int* cs = g_csr + st;
    const __half2* gb = g_ggh + 2 * t;   // (mu,ls) pairs j=2t, 2t+1
    float a0x=0.f,a0y=0.f,a0z=0.f,a0w=0.f, a1x=0.f,a1y=0.f,a1z=0.f,a1w=0.f;
    int e = 0;
    for (; e + 4 <= cnt; e += 4) {
        int s0 = cs[e], s1 = cs[e+1], s2 = cs[e+2], s3 = cs[e+3];
        uint2 u0 = *(const uint2*)(gb + (size_t)s0 * 32);
        uint2 u1 = *(const uint2*)(gb + (size_t)s1 * 32);
        uint2 u2 = *(const uint2*)(gb + (size_t)s2 * 32);
        uint2 u3 = *(const uint2*)(gb + (size_t)s3 * 32);
        float2 p0 = __half22float2(*(__half2*)&u0.x), q0 = __half22float2(*(__half2*)&u0.y);
        float2 p1 = __half22float2(*(__half2*)&u1.x), q1 = __half22float2(*(__half2*)&u1.y);
        float2 p2 = __half22float2(*(__half2*)&u2.x), q2 = __half22float2(*(__half2*)&u2.y);
        float2 p3 = __half22float2(*(__half2*)&u3.x), q3 = __half22float2(*(__half2*)&u3.y);
        a0x += p0.x; a0y += p0.y; a0z += q0.x; a0w += q0.y;
        a1x += p1.x; a1y += p1.y; a1z += q1.x; a1w += q1.y;
        a0x += p2.x; a0y += p2.y; a0z += q2.x; a0w += q2.y;
        a1x += p3.x; a1y += p3.y; a1z += q3.x; a1w += q3.y;
    }
    for (; e < cnt; e++) {
        uint2 u = *(const uint2*)(gb + (size_t)cs[e] * 32);
        float2 p = __half22float2(*(__half2*)&u.x), q = __half22float2(*(__half2*)&u.y);
        a0x += p.x; a0y += p.y; a0z += q.x; a0w += q.y;
    }
    if (!valid) return;                  // no shuffles below — safe to exit
    uint2 us = *(const uint2*)(gb + (size_t)nd * 32);
    float2 ps = __half22float2(*(__half2*)&us.x), qs = __half22float2(*(__half2*)&us.y);
    float di = g_dis[nd];
    // pair j=2t:   mu0 = di*(a0x+a1x+ps.x)+bmu[2t],  ls0 = di*(a0y+a1y+ps.y)+bls[2t]
    // pair j=2t+1: mu1, ls1 analogously
    float mu0 = fmaf(di, a0x + a1x + ps.x, bmu[2*t]);
    float ls0 = fmaf(di, a0y + a1y + ps.y, bls[2*t]);
    float mu1 = fmaf(di, a0z + a1z + qs.x, bmu[2*t+1]);
    float ls1 = fmaf(di, a0w + a1w + qs.y, bls[2*t+1]);
    size_t oi = (size_t)nd * 32 + 2*t;
    *(float2*)(out_mu + oi) = make_float2(mu0, mu1);
    *(float2*)(out_ls + oi) = make_float2(ls0, ls1);
    float2 ep = *(const float2*)(eps + oi);
    float lc0 = fminf(fmaxf(ls0, -10.f), 10.f);
    float lc1 = fminf(fmaxf(ls1, -10.f), 10.f);
    float z0 = fmaf(ep.x, __expf(lc0), mu0);
    float z1 = fmaf(ep.y, __expf(lc1), mu1);
    *(__half2*)(g_zh + oi) = __floats2half2_rn(z0, z1);
}

// ---------------- decode: 4 lanes/edge, uint4 (16B) loads ----------------
__global__ void __launch_bounds__(256) decode_kernel(const int* __restrict__ src,
                                                     const int* __restrict__ dst,
                                                     float* __restrict__ out, int E) {
    int gid = blockIdx.x * 256 + threadIdx.x;
    int e   = gid >> 2;
    int sub = gid & 3;
    if (e >= E) return;
    int s = src[e], d = dst[e];
    uint4 ua = *(const uint4*)(g_zh + (size_t)s * 32 + sub * 8);
    uint4 ub = *(const uint4*)(g_zh + (size_t)d * 32 + sub * 8);
    float2 a0 = __half22float2(*reinterpret_cast<__half2*>(&ua.x));
    float2 a1 = __half22float2(*reinterpret_cast<__half2*>(&ua.y));
    float2 a2 = __half22float2(*reinterpret_cast<__half2*>(&ua.z));
    float2 a3 = __half22float2(*reinterpret_cast<__half2*>(&ua.w));
    float2 b0 = __half22float2(*reinterpret_cast<__half2*>(&ub.x));
    float2 b1 = __half22float2(*reinterpret_cast<__half2*>(&ub.y));
    float2 b2 = __half22float2(*reinterpret_cast<__half2*>(&ub.z));
    float2 b3 = __half22float2(*reinterpret_cast<__half2*>(&ub.w));
    float p = a0.x*b0.x + a0.y*b0.y + a1.x*b1.x + a1.y*b1.y
            + a2.x*b2.x + a2.y*b2.y + a3.x*b3.x + a3.y*b3.y;
    p += __shfl_xor_sync(0xffffffffu, p, 1);
    p += __shfl_xor_sync(0xffffffffu, p, 2);
    if (sub == 0) out[e] = 1.0f / (1.0f + __expf(-p));
}

// ---------------- launch ----------------
extern "C" void kernel_launch(void* const* d_in, const int* in_sizes, int n_in,
                              void* d_out, int out_size) {
    const float* x   = (const float*)d_in[0];
    const int*   ei  = (const int*)  d_in[1];
    const float* eps = (const float*)d_in[2];
    const float* W1  = (const float*)d_in[3];
    const float* b1  = (const float*)d_in[4];
    const float* Wmu = (const float*)d_in[5];
    const float* bmu = (const float*)d_in[6];
    const float* Wls = (const float*)d_in[7];
    const float* bls = (const float*)d_in[8];

    int n = in_sizes[0] / 128;
    int E = in_sizes[1] / 2;
    const int* src = ei;
    const int* dst = ei + E;

    float* out     = (float*)d_out;
    float* out_adj = out;
    float* out_mu  = out + E;
    float* out_ls  = out + E + (size_t)n * 32;

    const int SMEM1 = (4096 + 4096 + 32 * 132) * 4;   // 49664
    const int SMEM2 = (2048 + 2048 + 32 * 132) * 4;   // 33280
    cudaFuncSetAttribute(gemm1_kernel, cudaFuncAttributeMaxDynamicSharedMemorySize, SMEM1);
    cudaFuncSetAttribute(gemm2_kernel, cudaFuncAttributeMaxDynamicSharedMemorySize, SMEM2);

    cudaStream_t s2;
    cudaEvent_t evFork, evJoin;
    cudaStreamCreateWithFlags(&s2, cudaStreamNonBlocking);
    cudaEventCreateWithFlags(&evFork, cudaEventDisableTiming);
    cudaEventCreateWithFlags(&evJoin, cudaEventDisableTiming);

    init_kernel<<<(n + 255) / 256, 256>>>(n);
    hist_kernel<<<(E + 255) / 256, 256>>>(dst, E);
    dis_kernel<<<(n + 255) / 256, 256>>>(n);

    // fork: gemm1 depends only on {x, W1, dis}
    cudaEventRecord(evFork, 0);
    cudaStreamWaitEvent(s2, evFork, 0);
    gemm1_kernel<<<(n + 127) / 128, 256, SMEM1, s2>>>(x, W1, n);
    cudaEventRecord(evJoin, s2);

    int nb = (n + 1023) / 1024;
    scan1_kernel<<<nb, 1024>>>(n);
    scan2_kernel<<<1, 256>>>(nb);
    scan3_kernel<<<(n + 255) / 256, 256>>>(n);
    fill_kernel<<<(E + 255) / 256, 256>>>(src, dst, E);

    cudaStreamWaitEvent(0, evJoin, 0);

    conv1_kernel<<<(n + 15) / 16, 256>>>(b1, n);
    gemm2_kernel<<<(n + 127) / 128, 256, SMEM2>>>(Wmu, Wls, n);
    conv2_kernel<<<(n + 15) / 16, 256>>>(bmu, bls, eps, out_mu, out_ls, n);
    decode_kernel<<<((size_t)E * 4 + 255) / 256, 256>>>(src, dst, out_adj, E);
}